// round 15
// baseline (speedup 1.0000x reference)
#include <cuda_runtime.h>
#include <cuda_bf16.h>
#include <cstdint>

#define W 512
#define H 512
#define IMGS 128
#define STRIPB 64                      // rows per CTA
#define STRIPS (H / STRIPB)            // 8
#define BLOCK 128
#define WPB 4
#define GRID (IMGS * STRIPS)           // 1024
#define CPT 8
#define NELEM 33554432.0f
#define FULLM 0xffffffffu

#define CHROWS 3
#define CHB (CHROWS * W * 4)           // 6144
#define RINGN 2
#define PIPEB (RINGN * CHB)            // 12288

__device__ float g_partials[GRID];
__device__ unsigned int g_count;

__device__ __forceinline__ void mbar_init(unsigned bar, unsigned cnt) {
    asm volatile("mbarrier.init.shared.b64 [%0], %1;" :: "r"(bar), "r"(cnt) : "memory");
}
__device__ __forceinline__ void mbar_wait(unsigned bar, unsigned parity) {
    asm volatile(
        "{\n\t.reg .pred P;\n\t"
        "WL_%=:\n\t"
        "mbarrier.try_wait.parity.acquire.cta.shared::cta.b64 P, [%0], %1, 0x989680;\n\t"
        "@P bra.uni WD_%=;\n\t"
        "bra.uni WL_%=;\n\t"
        "WD_%=:\n\t}"
        :: "r"(bar), "r"(parity) : "memory");
}
__device__ __forceinline__ void mbar_arrive(unsigned bar) {
    asm volatile("mbarrier.arrive.shared.b64 _, [%0];" :: "r"(bar) : "memory");
}
__device__ __forceinline__ void mbar_expect(unsigned bar, unsigned bytes) {
    asm volatile("mbarrier.arrive.expect_tx.shared.b64 _, [%0], %1;"
                 :: "r"(bar), "r"(bytes) : "memory");
}
__device__ __forceinline__ void bulk_cp(unsigned dst, const float* src, unsigned bytes,
                                        unsigned bar) {
    asm volatile("cp.async.bulk.shared::cta.global.mbarrier::complete_tx::bytes "
                 "[%0], [%1], %2, [%3];"
                 :: "r"(dst), "l"(src), "r"(bytes), "r"(bar) : "memory");
}

struct Carry {
    float xp[CPT];
    float erp[CPT];
    float xLp, xRp;
    float erpR;
};

__device__ __forceinline__ void step_compute(const float xc[CPT], float xLc, float xRc,
                                             int lane, bool rightEdge,
                                             Carry& C, float& acc) {
    float vm[CPT];
#pragma unroll
    for (int i = 0; i < CPT; i++) vm[i] = fminf(C.xp[i], xc[i]);
    float vmL = fminf(C.xLp, xLc);
    float vmR = fminf(C.xRp, xRc);

    float left = __shfl_up_sync(FULLM, vm[CPT-1], 1);
    if (lane == 0) left = vmL;
    float ern[CPT];
    ern[0] = fminf(left, vm[0]);
#pragma unroll
    for (int i = 1; i < CPT; i++) ern[i] = fminf(vm[i-1], vm[i]);
    float ernR = fminf(vm[CPT-1], vmR);

    float h[CPT];
#pragma unroll
    for (int i = 0; i < CPT; i++) h[i] = fmaxf(C.erp[i], ern[i]);
    float hR = fmaxf(C.erpR, ernR);

    float hn = __shfl_down_sync(FULLM, h[0], 1);
    if (lane == 31) hn = rightEdge ? h[CPT-1] : hR;
#pragma unroll
    for (int i = 0; i < CPT-1; i++) {
        float di = fmaxf(h[i], h[i+1]);
        float d = C.xp[i] - di;
        acc = fmaf(d, d, acc);
    }
    {
        float di = fmaxf(h[CPT-1], hn);
        float d = C.xp[CPT-1] - di;
        acc = fmaf(d, d, acc);
    }

#pragma unroll
    for (int i = 0; i < CPT; i++) { C.xp[i] = xc[i]; C.erp[i] = ern[i]; }
    C.xLp = xLc; C.xRp = xRc; C.erpR = ernR;
}

__device__ __forceinline__ void final_emit(int lane, bool rightEdge, Carry& C, float& acc) {
    float hn = __shfl_down_sync(FULLM, C.erp[0], 1);
    if (lane == 31) hn = rightEdge ? C.erp[CPT-1] : C.erpR;
#pragma unroll
    for (int i = 0; i < CPT-1; i++) {
        float di = fmaxf(C.erp[i], C.erp[i+1]);
        float d = C.xp[i] - di;
        acc = fmaf(d, d, acc);
    }
    float di = fmaxf(C.erp[CPT-1], hn);
    float d = C.xp[CPT-1] - di;
    acc = fmaf(d, d, acc);
}

__global__ void __launch_bounds__(BLOCK, 7)
opening_loss_kernel(const float* __restrict__ labels, float* __restrict__ out) {
    __shared__ __align__(16) char sdata[2 * PIPEB];            // 24576 B
    __shared__ __align__(8) unsigned long long mbars[8];

    const int lane = threadIdx.x & 31;
    const int wid  = threadIdx.x >> 5;
    const int pipe = wid >> 1;
    const int cw   = wid & 1;

    const int img   = blockIdx.x >> 3;
    const int strip = blockIdx.x & (STRIPS - 1);
    const int r0 = strip * STRIPB;
    const float* base = labels + (size_t)img * (W * H);

    const unsigned mb0 = (unsigned)__cvta_generic_to_shared(mbars);
    if (threadIdx.x == 0) {
#pragma unroll
        for (int p = 0; p < 2; p++) {
            mbar_init(mb0 + (p*4+0)*8u, 1u);   // full stage 0
            mbar_init(mb0 + (p*4+1)*8u, 1u);   // full stage 1
            mbar_init(mb0 + (p*4+2)*8u, 2u);   // empty stage 0
            mbar_init(mb0 + (p*4+3)*8u, 2u);   // empty stage 1
        }
    }
    __syncthreads();

    const bool p1 = (pipe == 1);
    const bool lastStrip = (r0 + STRIPB == H);
    const bool strip0 = (strip == 0);
    const bool dupInit = (!p1 && strip0);                // x[-1]=x[0] at top edge
    const bool has33 = !(dupInit || (p1 && lastStrip));  // is j=33 a valid step?
    const int NC = has33 ? 12 : 11;                      // chunks fetched

    const int rA = p1 ? (r0 + 31) : ((r0 > 0) ? r0 - 1 : 0);
    const unsigned psm = (unsigned)__cvta_generic_to_shared(sdata) + pipe * PIPEB;
    const unsigned fullb  = mb0 + (unsigned)(pipe*4)   * 8u;
    const unsigned emptyb = mb0 + (unsigned)(pipe*4+2) * 8u;

    auto produce = [&](int n) {
        if (n < NC) {
            if (n >= RINGN)
                mbar_wait(emptyb + (unsigned)(n & 1) * 8u, (unsigned)(((n >> 1) - 1) & 1));
            if (lane == 0) {
                int st = rA + n * CHROWS;
                if (st > H - CHROWS) st = H - CHROWS;     // clamp (tail only)
                mbar_expect(fullb + (unsigned)(n & 1) * 8u, CHB);
                bulk_cp(psm + (unsigned)(n & 1) * CHB,
                        base + (size_t)st * W, CHB,
                        fullb + (unsigned)(n & 1) * 8u);
            }
            __syncwarp();
        }
    };

    if (cw == 0) {
        if (lane == 0)
            asm volatile("fence.proxy.async.shared::cta;" ::: "memory");
        __syncwarp();
        produce(0);
        produce(1);
    }

    const int c0 = cw * 256;
    const bool rightEdge = (cw == 1);
    const int cL = (c0 == 0) ? 0 : c0 - 1;
    const int cR = c0 + 256;                  // only read when !rightEdge
    const int tcol = c0 + lane * CPT;

    const char* pipebase = sdata + pipe * PIPEB;

    auto read_slot = [&](const char* p, float x[CPT], float& xL, float& xR) {
        float4 a = *reinterpret_cast<const float4*>(p + tcol * 4);
        float4 b = *reinterpret_cast<const float4*>(p + tcol * 4 + 16);
        x[0]=a.x; x[1]=a.y; x[2]=a.z; x[3]=a.w;
        x[4]=b.x; x[5]=b.y; x[6]=b.z; x[7]=b.w;
        xL = (lane == 0)                ? *reinterpret_cast<const float*>(p + cL * 4) : 0.0f;
        xR = (!rightEdge && lane == 31) ? *reinterpret_cast<const float*>(p + cR * 4) : 0.0f;
    };

    Carry C;
    float acc = 0.0f;

    // ── chunk 0 (peeled): init carry + early body steps ──
    mbar_wait(fullb, 0u);
    {
        float xa[CPT], xb[CPT], xLa, xRa, xLb, xRb;
        read_slot(pipebase, xa, xLa, xRa);                    // j=0
        if (!dupInit) {
            read_slot(pipebase + 2048, xb, xLb, xRb);         // j=1
        } else {
#pragma unroll
            for (int i = 0; i < CPT; i++) xb[i] = xa[i];
            xLb = xLa; xRb = xRa;
        }
        float vm[CPT];
#pragma unroll
        for (int i = 0; i < CPT; i++) vm[i] = fminf(xa[i], xb[i]);
        float vmL = fminf(xLa, xLb);
        float vmR = fminf(xRa, xRb);
        float left = __shfl_up_sync(FULLM, vm[CPT-1], 1);
        if (lane == 0) left = vmL;
        C.erp[0] = fminf(left, vm[0]);
#pragma unroll
        for (int i = 1; i < CPT; i++) C.erp[i] = fminf(vm[i-1], vm[i]);
        C.erpR = fminf(vm[CPT-1], vmR);
#pragma unroll
        for (int i = 0; i < CPT; i++) C.xp[i] = xb[i];
        C.xLp = xLb; C.xRp = xRb;

        float xc[CPT], xLc, xRc;
        if (dupInit) {                                        // body j=1, j=2
            read_slot(pipebase + 2048, xc, xLc, xRc);
            step_compute(xc, xLc, xRc, lane, rightEdge, C, acc);
        }
        read_slot(pipebase + 4096, xc, xLc, xRc);             // body j=2
        step_compute(xc, xLc, xRc, lane, rightEdge, C, acc);
    }
    __syncwarp();
    if (lane == 0) mbar_arrive(emptyb);
    if (cw == 0) produce(2);

    // ── chunks 1..10: fully valid, unrolled slots ──
#pragma unroll 1
    for (int cc = 1; cc <= 10; cc++) {
        mbar_wait(fullb + (unsigned)(cc & 1) * 8u, (unsigned)((cc >> 1) & 1));
        const char* cb = pipebase + (cc & 1) * CHB;
#pragma unroll
        for (int s = 0; s < CHROWS; s++) {
            float xc[CPT], xLc, xRc;
            read_slot(cb + s * 2048, xc, xLc, xRc);
            step_compute(xc, xLc, xRc, lane, rightEdge, C, acc);
        }
        __syncwarp();
        if (lane == 0) mbar_arrive(emptyb + (unsigned)(cc & 1) * 8u);
        if (cw == 0) produce(cc + 2);
    }

    // ── chunk 11: single guarded step (j=33) ──
    if (has33) {
        mbar_wait(fullb + 8u, 1u);                            // cc=11: stage1, phase1
        float xc[CPT], xLc, xRc;
        read_slot(pipebase + CHB, xc, xLc, xRc);
        step_compute(xc, xLc, xRc, lane, rightEdge, C, acc);
    }
    if (p1 && lastStrip) final_emit(lane, rightEdge, C, acc); // emit row 511

    // ── deterministic reduction ──
#pragma unroll
    for (int off = 16; off; off >>= 1)
        acc += __shfl_xor_sync(FULLM, acc, off);

    __shared__ float s[WPB];
    __shared__ bool is_last;
    if (lane == 0) s[wid] = acc;
    __syncthreads();
    if (threadIdx.x == 0) {
        float tsum = 0.0f;
#pragma unroll
        for (int i = 0; i < WPB; i++) tsum += s[i];
        g_partials[blockIdx.x] = tsum;
        __threadfence();
        unsigned v = atomicAdd(&g_count, 1u);
        is_last = (v == GRID - 1);
    }
    __syncthreads();

    if (is_last) {
        __shared__ float r[BLOCK];
        float v = 0.0f;
#pragma unroll
        for (int k = 0; k < GRID / BLOCK; k++)
            v += g_partials[threadIdx.x + k * BLOCK];
        r[threadIdx.x] = v;
        __syncthreads();
#pragma unroll
        for (int off = BLOCK / 2; off > 0; off >>= 1) {
            if (threadIdx.x < off) r[threadIdx.x] += r[threadIdx.x + off];
            __syncthreads();
        }
        if (threadIdx.x == 0) {
            out[0] = r[0] * (1.0f / NELEM);
            g_count = 0;
        }
    }
}

extern "C" void kernel_launch(void* const* d_in, const int* in_sizes, int n_in,
                              void* d_out, int out_size) {
    const float* labels = (const float*)d_in[0];
    float* out = (float*)d_out;
    opening_loss_kernel<<<GRID, BLOCK>>>(labels, out);
}